// round 8
// baseline (speedup 1.0000x reference)
#include <cuda_runtime.h>
#include <cuda_bf16.h>
#include <cstdint>

#define BB 2
#define NN 2048
#define DD 512
#define HH 8
#define HD 64
#define ROWS (BB*NN)

// Scratch (no allocations allowed)
__device__ __nv_bfloat16 g_QKV[3][(size_t)ROWS * DD];   // Q,K,V projections
__device__ __nv_bfloat16 g_Xb[(size_t)ROWS * DD];       // x in bf16
__device__ __nv_bfloat16 g_Wb[3][(size_t)DD * DD];      // W_q/k/v in bf16
__device__ float g_c[ROWS];                             // gate vec (pre-scaled by log2e)

#define LOG2E 1.4426950408889634f

// ---------------------------------------------------------------------------
// helpers
// ---------------------------------------------------------------------------
__device__ __forceinline__ float ex2f(float x) {        // 2^x on MUFU
    float r;
    asm("ex2.approx.f32 %0, %1;" : "=f"(r) : "f"(x));
    return r;
}
__device__ __forceinline__ uint32_t pack_bf16(float lo, float hi) {
    uint32_t r;
    asm("cvt.rn.bf16x2.f32 %0, %1, %2;" : "=r"(r) : "f"(hi), "f"(lo));
    return r;
}
__device__ __forceinline__ void mma16(float* d, const uint32_t* a,
                                      uint32_t b0, uint32_t b1, const float* c) {
    asm("mma.sync.aligned.m16n8k16.row.col.f32.bf16.bf16.f32 "
        "{%0,%1,%2,%3}, {%4,%5,%6,%7}, {%8,%9}, {%10,%11,%12,%13};"
        : "=f"(d[0]), "=f"(d[1]), "=f"(d[2]), "=f"(d[3])
        : "r"(a[0]), "r"(a[1]), "r"(a[2]), "r"(a[3]),
          "r"(b0), "r"(b1),
          "f"(c[0]), "f"(c[1]), "f"(c[2]), "f"(c[3]));
}
__device__ __forceinline__ void ldm_x4(uint32_t* r, const void* ptr) {
    uint32_t a = (uint32_t)__cvta_generic_to_shared(ptr);
    asm volatile("ldmatrix.sync.aligned.m8n8.x4.shared.b16 "
                 "{%0,%1,%2,%3}, [%4];"
                 : "=r"(r[0]), "=r"(r[1]), "=r"(r[2]), "=r"(r[3]) : "r"(a));
}
__device__ __forceinline__ void ldm_x4_trans(uint32_t* r, const void* ptr) {
    uint32_t a = (uint32_t)__cvta_generic_to_shared(ptr);
    asm volatile("ldmatrix.sync.aligned.m8n8.x4.trans.shared.b16 "
                 "{%0,%1,%2,%3}, [%4];"
                 : "=r"(r[0]), "=r"(r[1]), "=r"(r[2]), "=r"(r[3]) : "r"(a));
}
__device__ __forceinline__ void cpa16(void* smem_dst, const void* gsrc) {
    uint32_t d = (uint32_t)__cvta_generic_to_shared(smem_dst);
    asm volatile("cp.async.cg.shared.global [%0], [%1], 16;" :: "r"(d), "l"(gsrc));
}
#define CP_COMMIT asm volatile("cp.async.commit_group;" ::: "memory")
#define CP_WAIT1  asm volatile("cp.async.wait_group 1;" ::: "memory")
#define CP_WAIT0  asm volatile("cp.async.wait_group 0;" ::: "memory")

// ---------------------------------------------------------------------------
// Kernel 0: one-shot fp32 -> bf16 conversion of x and W_q/k/v.
// ---------------------------------------------------------------------------
__global__ __launch_bounds__(256)
void convert_kernel(const float* __restrict__ X, const float* __restrict__ Wq,
                    const float* __restrict__ Wk, const float* __restrict__ Wv)
{
    int idx = blockIdx.x * 256 + threadIdx.x;
    const float* src;
    __nv_bfloat16* dst;
    size_t off;
    if (idx < 262144) {
        src = X; dst = g_Xb; off = (size_t)idx * 8;
    } else {
        int r = idx - 262144;
        int z = r >> 15;
        int o = r & 32767;
        src = (z == 0) ? Wq : (z == 1) ? Wk : Wv;
        dst = g_Wb[z]; off = (size_t)o * 8;
    }
    float4 v0 = *(const float4*)(src + off);
    float4 v1 = *(const float4*)(src + off + 4);
    uint4 u;
    u.x = pack_bf16(v0.x, v0.y);
    u.y = pack_bf16(v0.z, v0.w);
    u.z = pack_bf16(v1.x, v1.y);
    u.w = pack_bf16(v1.z, v1.w);
    *(uint4*)(dst + off) = u;
}

// ---------------------------------------------------------------------------
// Kernel 1: fused QKV projection, pure bf16, cp.async double-buffered, BK=64.
// ---------------------------------------------------------------------------
__global__ __launch_bounds__(256)
void qkv_gemm(const float* __restrict__ bq, const float* __restrict__ bk,
              const float* __restrict__ bv)
{
    extern __shared__ __nv_bfloat16 dsm[];
    __nv_bfloat16* Xs[2] = {dsm, dsm + 128 * 72};
    __nv_bfloat16* Ws[2] = {dsm + 2 * 128 * 72, dsm + 2 * 128 * 72 + 64 * 72};

    int z = blockIdx.z;
    const __nv_bfloat16* Xg = g_Xb;
    const __nv_bfloat16* Wg = g_Wb[z];
    const float* bias = (z == 0) ? bq : (z == 1) ? bk : bv;
    __nv_bfloat16* C = g_QKV[z];

    int row0 = blockIdx.y * 128;
    int col0 = blockIdx.x * 64;
    int tid  = threadIdx.x;
    int warp = tid >> 5, lane = tid & 31;
    int g = lane >> 2, t4 = lane & 3;
    int wm = (warp & 3) * 32;
    int wn = (warp >> 2) * 32;

    int a_r = ((lane >> 3) & 1) * 8 + (lane & 7);
    int a_c = (lane >> 4) * 8;
    int v_r = (lane & 7) + ((lane >> 3) & 1) * 8;
    int v_s = lane >> 4;

    int xrw[4], xce[4];
    #pragma unroll
    for (int it = 0; it < 4; ++it) {
        int c = tid + it * 256;
        xrw[it] = c >> 3; xce[it] = (c & 7) * 8;
    }
    int wrw[2], wce[2];
    #pragma unroll
    for (int it = 0; it < 2; ++it) {
        int c = tid + it * 256;
        wrw[it] = c >> 3; wce[it] = (c & 7) * 8;
    }

    auto stage = [&](int kit, int buf) {
        int k0 = kit * 64;
        #pragma unroll
        for (int it = 0; it < 4; ++it)
            cpa16(&Xs[buf][xrw[it] * 72 + xce[it]],
                  Xg + (size_t)(row0 + xrw[it]) * DD + k0 + xce[it]);
        #pragma unroll
        for (int it = 0; it < 2; ++it)
            cpa16(&Ws[buf][wrw[it] * 72 + wce[it]],
                  Wg + (size_t)(k0 + wrw[it]) * DD + col0 + wce[it]);
    };

    float acc[2][4][4] = {};

    stage(0, 0); CP_COMMIT;

    for (int it = 0; it < 8; ++it) {
        int buf = it & 1;
        if (it < 7) { stage(it + 1, buf ^ 1); CP_COMMIT; CP_WAIT1; }
        else        { CP_WAIT0; }
        __syncthreads();

        #pragma unroll
        for (int ch = 0; ch < 4; ++ch) {
            int kk = ch * 16;
            uint32_t a[2][4];
            ldm_x4(a[0], &Xs[buf][(wm + a_r) * 72 + kk + a_c]);
            ldm_x4(a[1], &Xs[buf][(wm + 16 + a_r) * 72 + kk + a_c]);
            uint32_t b0[4], b1[4];
            ldm_x4_trans(b0, &Ws[buf][(kk + v_r) * 72 + wn + v_s * 8]);
            ldm_x4_trans(b1, &Ws[buf][(kk + v_r) * 72 + wn + 16 + v_s * 8]);
            #pragma unroll
            for (int m = 0; m < 2; ++m) {
                mma16(acc[m][0], a[m], b0[0], b0[1], acc[m][0]);
                mma16(acc[m][1], a[m], b0[2], b0[3], acc[m][1]);
                mma16(acc[m][2], a[m], b1[0], b1[1], acc[m][2]);
                mma16(acc[m][3], a[m], b1[2], b1[3], acc[m][3]);
            }
        }
        __syncthreads();
    }

    #pragma unroll
    for (int n = 0; n < 4; ++n) {
        int col = col0 + wn + n * 8 + 2 * t4;
        float2 bb = *(const float2*)(bias + col);
        #pragma unroll
        for (int m = 0; m < 2; ++m) {
            int r0 = row0 + wm + m * 16 + g;
            *(uint32_t*)(C + (size_t)r0 * DD + col) =
                pack_bf16(acc[m][n][0] + bb.x, acc[m][n][1] + bb.y);
            *(uint32_t*)(C + (size_t)(r0 + 8) * DD + col) =
                pack_bf16(acc[m][n][2] + bb.x, acc[m][n][3] + bb.y);
        }
    }
}

// ---------------------------------------------------------------------------
// Kernel 2: c[row] = (x[row] . w_g[D:2D]) * log2e
// ---------------------------------------------------------------------------
__global__ __launch_bounds__(256)
void gate_kernel(const float* __restrict__ x, const float* __restrict__ wg)
{
    int row  = blockIdx.x * 8 + (threadIdx.x >> 5);
    int lane = threadIdx.x & 31;
    const float* xr = x + (size_t)row * DD;
    const float* w2 = wg + DD;
    float s = 0.f;
    #pragma unroll 4
    for (int d = lane; d < DD; d += 32) s = fmaf(xr[d], w2[d], s);
    #pragma unroll
    for (int off = 16; off > 0; off >>= 1)
        s += __shfl_xor_sync(0xffffffffu, s, off);
    if (lane == 0) g_c[row] = s * LOG2E;
}

// ---------------------------------------------------------------------------
// Kernel 3: flash attention, bf16 mma. Each warp owns 32 query rows
// (2 m-tiles) so every K/V fragment load feeds TWO mma tiles -> K/V smem
// read duplication halves. CTA = 128 queries (4 warps), 64-key tiles,
// triple-buffered cp.async, P in registers, softmax log2-domain on MUFU.
// ---------------------------------------------------------------------------
__global__ __launch_bounds__(128, 2)
void attn_kernel(const float* __restrict__ x, const float* __restrict__ adj,
                 float* __restrict__ out)
{
    extern __shared__ __nv_bfloat16 asm_buf[];
    const int TB = 64 * 72;
    __nv_bfloat16* Kb0 = asm_buf;            // K buffers 0..2
    __nv_bfloat16* Vb0 = asm_buf + 3 * TB;   // V buffers 0..2

    int tid  = threadIdx.x;
    int warp = tid >> 5, lane = tid & 31;
    int g = lane >> 2, t4 = lane & 3;
    int qr = warp * 32;                      // warp's 32-row query base
    int i0 = blockIdx.x * 128;
    int h  = blockIdx.y;
    int b  = blockIdx.z;

    int a_r = ((lane >> 3) & 1) * 8 + (lane & 7);   // A non-trans (Q)
    int a_c = (lane >> 4) * 8;
    int k_r = (lane >> 4) * 8 + (lane & 7);         // B non-trans (K)
    int k_c = ((lane >> 3) & 1) * 8;
    int v_r = (lane & 7) + ((lane >> 3) & 1) * 8;   // B trans (V)
    int v_s = lane >> 4;

    const __nv_bfloat16* Qg = g_QKV[0] + (size_t)b * NN * DD + h * HD;
    const __nv_bfloat16* Kg = g_QKV[1] + (size_t)b * NN * DD + h * HD;
    const __nv_bfloat16* Vg = g_QKV[2] + (size_t)b * NN * DD + h * HD;
    const float* cv   = g_c + b * NN;
    const float* adjb = adj + (size_t)b * NN * NN;

    int srw[4], sce[4];
    #pragma unroll
    for (int it = 0; it < 4; ++it) {
        int c = tid + it * 128;
        srw[it] = c >> 3; sce[it] = (c & 7) * 8;
    }

    auto stage_kv = [&](int jt, int buf) {
        int j0 = jt * 64;
        #pragma unroll
        for (int it = 0; it < 4; ++it) {
            cpa16(Kb0 + buf * TB + srw[it] * 72 + sce[it],
                  Kg + (size_t)(j0 + srw[it]) * DD + sce[it]);
            cpa16(Vb0 + buf * TB + srw[it] * 72 + sce[it],
                  Vg + (size_t)(j0 + srw[it]) * DD + sce[it]);
        }
    };

    // ---- Stage Q (128x64) into K buffers 1+2 (contiguous); lift fragments ----
    __nv_bfloat16* Qs = Kb0 + TB;   // 128 rows x stride 72 spans Kb1..Kb2
    #pragma unroll
    for (int it = 0; it < 8; ++it) {
        int c = tid + it * 128;
        int r = c >> 3, c8 = (c & 7) * 8;
        uint4 v = *(const uint4*)(Qg + (size_t)(i0 + r) * DD + c8);
        *(uint4*)&Qs[r * 72 + c8] = v;
    }
    stage_kv(0, 0); CP_COMMIT;
    __syncthreads();

    uint32_t qa[2][4][4];
    #pragma unroll
    for (int m = 0; m < 2; ++m)
        #pragma unroll
        for (int ch = 0; ch < 4; ++ch)
            ldm_x4(qa[m][ch], &Qs[(qr + m * 16 + a_r) * 72 + ch * 16 + a_c]);
    __syncthreads();   // all warps done reading Q before iter-0/1 staging reuses Kb1/Kb2

    const float SC = 0.125f * LOG2E;
    float mx[2][2], lsum[2][2];
    #pragma unroll
    for (int m = 0; m < 2; ++m) {
        mx[m][0] = -1e30f; mx[m][1] = -1e30f;
        lsum[m][0] = 0.f;  lsum[m][1] = 0.f;
    }
    float o[2][8][4] = {};

    for (int jt = 0; jt < NN / 64; ++jt) {
        int j0 = jt * 64;
        int buf = jt % 3;
        if (jt + 1 < NN / 64) { stage_kv(jt + 1, (jt + 1) % 3); CP_COMMIT; CP_WAIT1; }
        else                  { CP_WAIT0; }
        __syncthreads();

        const __nv_bfloat16* Kt = Kb0 + buf * TB;
        const __nv_bfloat16* Vt = Vb0 + buf * TB;

        // ---- S = Q K^T for both m-tiles; each K fragment used twice ----
        float s[2][8][4] = {};
        #pragma unroll
        for (int ch = 0; ch < 4; ++ch) {
            int kk = ch * 16;
            #pragma unroll
            for (int np = 0; np < 4; ++np) {
                uint32_t kb[4];
                ldm_x4(kb, &Kt[(np * 16 + k_r) * 72 + kk + k_c]);
                #pragma unroll
                for (int m = 0; m < 2; ++m) {
                    mma16(s[m][2 * np],     qa[m][ch], kb[0], kb[1], s[m][2 * np]);
                    mma16(s[m][2 * np + 1], qa[m][ch], kb[2], kb[3], s[m][2 * np + 1]);
                }
            }
        }

        // ---- softmax (log2 domain) + pack P into A-fragments, per m-tile ----
        uint32_t pa[2][4][4];
        float al[2][2];
        #pragma unroll
        for (int m = 0; m < 2; ++m) {
            float mt0 = -1e30f, mt1 = -1e30f;
            #pragma unroll
            for (int n = 0; n < 8; ++n) {
                float2 cc = *(const float2*)(cv + j0 + n * 8 + 2 * t4);
                s[m][n][0] = fmaf(s[m][n][0], SC, cc.x);
                s[m][n][1] = fmaf(s[m][n][1], SC, cc.y);
                s[m][n][2] = fmaf(s[m][n][2], SC, cc.x);
                s[m][n][3] = fmaf(s[m][n][3], SC, cc.y);
                mt0 = fmaxf(mt0, fmaxf(s[m][n][0], s[m][n][1]));
                mt1 = fmaxf(mt1, fmaxf(s[m][n][2], s[m][n][3]));
            }
            mt0 = fmaxf(mt0, __shfl_xor_sync(0xffffffffu, mt0, 1));
            mt0 = fmaxf(mt0, __shfl_xor_sync(0xffffffffu, mt0, 2));
            mt1 = fmaxf(mt1, __shfl_xor_sync(0xffffffffu, mt1, 1));
            mt1 = fmaxf(mt1, __shfl_xor_sync(0xffffffffu, mt1, 2));

            float m0n = fmaxf(mx[m][0], mt0), m1n = fmaxf(mx[m][1], mt1);
            al[m][0] = ex2f(mx[m][0] - m0n);
            al[m][1] = ex2f(mx[m][1] - m1n);
            mx[m][0] = m0n; mx[m][1] = m1n;

            float rs0 = 0.f, rs1 = 0.f;
            int r0 = i0 + qr + m * 16 + g, r1 = r0 + 8;
            #pragma unroll
            for (int ch = 0; ch < 4; ++ch) {
                #pragma unroll
                for (int w = 0; w < 2; ++w) {
                    int n = 2 * ch + w;
                    int jc = j0 + n * 8 + 2 * t4;
                    float2 ad0 = *(const float2*)(adjb + (size_t)r0 * NN + jc);
                    float2 ad1 = *(const float2*)(adjb + (size_t)r1 * NN + jc);
                    float p00 = ex2f(s[m][n][0] - mx[m][0]) * (ad0.x + 1e-9f);
                    float p01 = ex2f(s[m][n][1] - mx[m][0]) * (ad0.y + 1e-9f);
                    float p10 = ex2f(s[m][n][2] - mx[m][1]) * (ad1.x + 1e-9f);
                    float p11 = ex2f(s[m][n][3] - mx[m][1]) * (ad1.y + 1e-9f);
                    rs0 += p00 + p01; rs1 += p10 + p11;
                    pa[m][ch][2 * w]     = pack_bf16(p00, p01);
                    pa[m][ch][2 * w + 1] = pack_bf16(p10, p11);
                }
            }
            rs0 += __shfl_xor_sync(0xffffffffu, rs0, 1);
            rs0 += __shfl_xor_sync(0xffffffffu, rs0, 2);
            rs1 += __shfl_xor_sync(0xffffffffu, rs1, 1);
            rs1 += __shfl_xor_sync(0xffffffffu, rs1, 2);
            lsum[m][0] = lsum[m][0] * al[m][0] + rs0;
            lsum[m][1] = lsum[m][1] * al[m][1] + rs1;

            #pragma unroll
            for (int n = 0; n < 8; ++n) {
                o[m][n][0] *= al[m][0]; o[m][n][1] *= al[m][0];
                o[m][n][2] *= al[m][1]; o[m][n][3] *= al[m][1];
            }
        }

        // ---- O += P @ V; each V fragment used twice (both m-tiles) ----
        #pragma unroll
        for (int ch = 0; ch < 4; ++ch) {
            int kk = ch * 16;
            #pragma unroll
            for (int np = 0; np < 4; ++np) {
                uint32_t vb[4];
                ldm_x4_trans(vb, &Vt[(kk + v_r) * 72 + (2 * np + v_s) * 8]);
                #pragma unroll
                for (int m = 0; m < 2; ++m) {
                    mma16(o[m][2 * np],     pa[m][ch], vb[0], vb[1], o[m][2 * np]);
                    mma16(o[m][2 * np + 1], pa[m][ch], vb[2], vb[3], o[m][2 * np + 1]);
                }
            }
        }
    }

    // ---- epilogue: normalize + residual (fp32) ----
    #pragma unroll
    for (int m = 0; m < 2; ++m) {
        float inv0 = __fdividef(1.0f, lsum[m][0]);
        float inv1 = __fdividef(1.0f, lsum[m][1]);
        int r0 = i0 + qr + m * 16 + g, r1 = r0 + 8;
        #pragma unroll
        for (int n = 0; n < 8; ++n) {
            int col = h * HD + n * 8 + 2 * t4;
            float2 x0 = *(const float2*)(x + ((size_t)b * NN + r0) * DD + col);
            float2 x1 = *(const float2*)(x + ((size_t)b * NN + r1) * DD + col);
            float2 o0 = {fmaf(o[m][n][0], inv0, x0.x), fmaf(o[m][n][1], inv0, x0.y)};
            float2 o1 = {fmaf(o[m][n][2], inv1, x1.x), fmaf(o[m][n][3], inv1, x1.y)};
            *(float2*)(out + ((size_t)b * NN + r0) * DD + col) = o0;
            *(float2*)(out + ((size_t)b * NN + r1) * DD + col) = o1;
        }
    }
}

// ---------------------------------------------------------------------------
extern "C" void kernel_launch(void* const* d_in, const int* in_sizes, int n_in,
                              void* d_out, int out_size)
{
    const float* x   = (const float*)d_in[0];
    const float* adj = (const float*)d_in[1];
    const float* Wq  = (const float*)d_in[2];
    const float* bq  = (const float*)d_in[3];
    const float* Wk  = (const float*)d_in[4];
    const float* bk  = (const float*)d_in[5];
    const float* Wv  = (const float*)d_in[6];
    const float* bv  = (const float*)d_in[7];
    const float* wg  = (const float*)d_in[8];
    // d_in[9] (b_g) cancels inside the softmax; unused.
    float* out = (float*)d_out;

    const int qkv_smem = (2 * 128 * 72 + 2 * 64 * 72) * 2;   // 55296 B
    cudaFuncSetAttribute((const void*)qkv_gemm,
                         cudaFuncAttributeMaxDynamicSharedMemorySize, qkv_smem);
    const int attn_smem = 6 * 64 * 72 * 2;                   // 55296 B
    cudaFuncSetAttribute((const void*)attn_kernel,
                         cudaFuncAttributeMaxDynamicSharedMemorySize, attn_smem);

    convert_kernel<<<1408, 256>>>(x, Wq, Wk, Wv);
    gate_kernel<<<ROWS / 8, 256>>>(x, wg);
    qkv_gemm<<<dim3(DD / 64, ROWS / 128, 3), 256, qkv_smem>>>(bq, bk, bv);
    attn_kernel<<<dim3(NN / 128, HH, BB), 128, attn_smem>>>(x, adj, out);
}